// round 7
// baseline (speedup 1.0000x reference)
#include <cuda_runtime.h>
#include <math.h>
#include <cstdint>

#define B_    2
#define T_    2048
#define NTOK  4096
#define DIM_  1024
#define HID_  4096
#define NH_   16
#define HD_   64

// Scratch (allocation-free rule: __device__ globals)
__device__ float g_h1 [NTOK * DIM_];
__device__ float g_qkv[NTOK * 3 * DIM_];
__device__ float g_att[NTOK * DIM_];
__device__ float g_x2 [NTOK * DIM_];
__device__ float g_h2 [NTOK * DIM_];
__device__ float g_f1 [NTOK * HID_];
// tf32-rounded TRANSPOSED weights [N,K]
__device__ float g_wq [3 * DIM_ * DIM_];
__device__ float g_wp [DIM_ * DIM_];
__device__ float g_w1 [HID_ * DIM_];
__device__ float g_w2 [DIM_ * HID_];

__device__ __forceinline__ unsigned f2tf32(float f) {
    unsigned u;
    asm("cvt.rna.tf32.f32 %0, %1;" : "=r"(u) : "f"(f));
    return u;
}
__device__ __forceinline__ float rtf32(float f) {
    return __uint_as_float(f2tf32(f));
}

// ---------------------------------------------------------------------------
// Transpose + tf32-round weights: in [K,N] -> out [N,K]
// ---------------------------------------------------------------------------
__global__ __launch_bounds__(256) void transpose_tf32(
    const float* __restrict__ in, float* __restrict__ out, int K, int N)
{
    __shared__ float t[32][33];
    int k0 = blockIdx.x * 32, n0 = blockIdx.y * 32;
    int tx = threadIdx.x & 31, ty = threadIdx.x >> 5;   // 32 x 8
#pragma unroll
    for (int dy = ty; dy < 32; dy += 8)
        t[dy][tx] = in[(size_t)(k0 + dy) * N + n0 + tx];
    __syncthreads();
#pragma unroll
    for (int dy = ty; dy < 32; dy += 8)
        out[(size_t)(n0 + dy) * K + k0 + tx] = rtf32(t[tx][dy]);
}

// ---------------------------------------------------------------------------
// LayerNorm: one block per row, 256 threads. Output rounded to tf32.
// ---------------------------------------------------------------------------
__global__ __launch_bounds__(256) void ln_kernel(
    const float* __restrict__ x, const float* __restrict__ w,
    const float* __restrict__ b, float* __restrict__ y)
{
    int row = blockIdx.x;
    const float* xr = x + (size_t)row * DIM_;
    float s = 0.f, s2 = 0.f;
    for (int i = threadIdx.x; i < DIM_; i += 256) {
        float v = xr[i]; s += v; s2 += v * v;
    }
    __shared__ float rs[8], rs2[8];
    for (int o = 16; o; o >>= 1) {
        s  += __shfl_down_sync(0xffffffffu, s,  o);
        s2 += __shfl_down_sync(0xffffffffu, s2, o);
    }
    int wid = threadIdx.x >> 5, lane = threadIdx.x & 31;
    if (!lane) { rs[wid] = s; rs2[wid] = s2; }
    __syncthreads();
    __shared__ float mu_s, inv_s;
    if (threadIdx.x == 0) {
        float t = 0.f, t2 = 0.f;
        for (int i = 0; i < 8; i++) { t += rs[i]; t2 += rs2[i]; }
        float mu = t / (float)DIM_;
        float var = t2 / (float)DIM_ - mu * mu;
        mu_s = mu;
        inv_s = rsqrtf(var + 1e-5f);
    }
    __syncthreads();
    float mu = mu_s, inv = inv_s;
    float* yr = y + (size_t)row * DIM_;
    for (int i = threadIdx.x; i < DIM_; i += 256)
        yr[i] = rtf32((xr[i] - mu) * inv * w[i] + b[i]);
}

// ---------------------------------------------------------------------------
// TF32 HMMA GEMM with ldmatrix fragment loads + cp.async 3-stage ring.
//   A operand = X  [M tokens, K]  (tf32-rounded activations, K-major)
//   B operand = Wt [N feats,  K]  (tf32-rounded transposed weights, K-major)
// CTA tile 128 tok x 256 feat, BK=16, 8 warps (2x4), warp tile 64x64.
// Rows stored with stride 20 words -> LDSM reads perfectly bank-partitioned.
// EPI: 0 none | 1 +bias+residual | 2 +bias+GELU(+tf32 round)
// ---------------------------------------------------------------------------
__device__ __forceinline__ void mma_tf32(float* c, const unsigned* a,
                                         const unsigned* b) {
    asm volatile(
        "mma.sync.aligned.m16n8k8.row.col.f32.tf32.tf32.f32 "
        "{%0,%1,%2,%3}, {%4,%5,%6,%7}, {%8,%9}, {%0,%1,%2,%3};"
        : "+f"(c[0]), "+f"(c[1]), "+f"(c[2]), "+f"(c[3])
        : "r"(a[0]), "r"(a[1]), "r"(a[2]), "r"(a[3]),
          "r"(b[0]), "r"(b[1]));
}

#define BM 128
#define BN 256
#define BKk 16
#define RSTR 20
#define SA  (BM * RSTR)          // 2560 words
#define SBW (BN * RSTR)          // 5120 words
#define SW  (SA + SBW)           // 7680 words
#define NSTAGE 3
#define GEMM_SMEM (NSTAGE * SW * 4)   // 92160 B

#define CPASYNC16(dst, src) \
    asm volatile("cp.async.cg.shared.global [%0], [%1], 16;" \
                 :: "r"(dst), "l"(src))

template <int EPI>
__global__ __launch_bounds__(256, 1) void gemm_tc(
    const float* __restrict__ X, const float* __restrict__ Wt,
    const float* __restrict__ bias, const float* __restrict__ res,
    float* __restrict__ C, int M, int N, int K)
{
    extern __shared__ float smf[];
    unsigned sbase = (unsigned)__cvta_generic_to_shared(smf);

    int tid = threadIdx.x, lane = tid & 31, warp = tid >> 5;
    int wr = warp >> 2, wc = warp & 3;           // 2x4 warp grid, 64x64
    int row0 = blockIdx.y * BM, col0 = blockIdx.x * BN;
    int g = lane >> 2, t = lane & 3;

    const float* Ab = X  + (size_t)row0 * K;
    const float* Wb = Wt + (size_t)col0 * K;

    // ldmatrix per-lane offsets (bytes, within a stage)
    int lg = lane & 7, sub = lane >> 3;
    unsigned aoff = (unsigned)((wr * 64 + lg + 8 * (sub & 1)) * RSTR
                               + 4 * (sub >> 1)) * 4u;
    int l16 = lane & 15;
    unsigned woff = (unsigned)((wc * 64 + (l16 & 7)) * RSTR
                               + 4 * (l16 >> 3)) * 4u;

    float acc[4][8][4] = {};
    int iters = K / BKk;

    // ---- producer: A 512 chunks (2/thr), W 1024 chunks (4/thr) ----
#define LOAD_STAGE(st, kt) do {                                            \
        unsigned sa_ = sbase + (unsigned)((st) * SW) * 4u;                 \
        unsigned sw_ = sa_ + SA * 4u;                                      \
        int kof = (kt) * BKk;                                              \
        _Pragma("unroll")                                                  \
        for (int p = 0; p < 2; p++) {                                      \
            int id = tid + 256 * p, r = id >> 2, c = id & 3;               \
            CPASYNC16(sa_ + (unsigned)(r * RSTR + c * 4) * 4u,             \
                      Ab + (size_t)r * K + kof + c * 4);                   \
        }                                                                  \
        _Pragma("unroll")                                                  \
        for (int p = 0; p < 4; p++) {                                      \
            int id = tid + 256 * p, r = id >> 2, c = id & 3;               \
            CPASYNC16(sw_ + (unsigned)(r * RSTR + c * 4) * 4u,             \
                      Wb + (size_t)r * K + kof + c * 4);                   \
        }                                                                  \
    } while (0)

#pragma unroll
    for (int s = 0; s < NSTAGE - 1; s++) {
        LOAD_STAGE(s, s);
        asm volatile("cp.async.commit_group;");
    }

    for (int it = 0; it < iters; it++) {
        asm volatile("cp.async.wait_group 1;");
        __syncthreads();

        int nk = it + NSTAGE - 1;
        if (nk < iters) LOAD_STAGE(nk % NSTAGE, nk);
        asm volatile("cp.async.commit_group;");

        unsigned sa = sbase + (unsigned)((it % NSTAGE) * SW) * 4u;
        unsigned sw = sa + SA * 4u;
#pragma unroll
        for (int ks = 0; ks < 2; ks++) {
            unsigned kb = (unsigned)(ks * 8) * 4u;
            unsigned af[4][4], bf[8][2];
#pragma unroll
            for (int mt = 0; mt < 4; mt++) {
                unsigned ad = sa + aoff + (unsigned)(mt * 16 * RSTR) * 4u + kb;
                asm volatile(
                    "ldmatrix.sync.aligned.m8n8.x4.shared.b16 "
                    "{%0,%1,%2,%3}, [%4];"
                    : "=r"(af[mt][0]), "=r"(af[mt][1]),
                      "=r"(af[mt][2]), "=r"(af[mt][3])
                    : "r"(ad));
            }
#pragma unroll
            for (int nt = 0; nt < 8; nt++) {
                unsigned wd = sw + woff + (unsigned)(nt * 8 * RSTR) * 4u + kb;
                asm volatile(
                    "ldmatrix.sync.aligned.m8n8.x2.shared.b16 {%0,%1}, [%2];"
                    : "=r"(bf[nt][0]), "=r"(bf[nt][1])
                    : "r"(wd));
            }
#pragma unroll
            for (int mt = 0; mt < 4; mt++)
#pragma unroll
                for (int nt = 0; nt < 8; nt++)
                    mma_tf32(acc[mt][nt], af[mt], bf[nt]);
        }
    }
#undef LOAD_STAGE

    // ---- epilogue ----
#pragma unroll
    for (int mt = 0; mt < 4; mt++) {
#pragma unroll
        for (int nt = 0; nt < 8; nt++) {
            int r = row0 + wr * 64 + mt * 16 + g;
            int c = col0 + wc * 64 + nt * 8 + t * 2;
#pragma unroll
            for (int half = 0; half < 2; half++) {
                int rr = r + half * 8;
                float v0 = acc[mt][nt][half * 2 + 0];
                float v1 = acc[mt][nt][half * 2 + 1];
                if (EPI == 1) {
                    const float* rp = res + (size_t)rr * N + c;
                    v0 += bias[c]     + rp[0];
                    v1 += bias[c + 1] + rp[1];
                } else if (EPI == 2) {
                    v0 += bias[c];
                    v1 += bias[c + 1];
                    v0 = 0.5f * v0 * (1.f + erff(v0 * 0.70710678118654752f));
                    v1 = 0.5f * v1 * (1.f + erff(v1 * 0.70710678118654752f));
                    v0 = rtf32(v0);
                    v1 = rtf32(v1);
                }
                *(float2*)(C + (size_t)rr * N + c) = make_float2(v0, v1);
            }
        }
    }
}

// ---------------------------------------------------------------------------
// Tensor-core flash attention (tf32 HMMA), causal + key-padding (R5).
// ---------------------------------------------------------------------------
#define QT 128
#define KT 64
#define AST 72
#define ATTN_SMEM ((QT*AST + KT*AST + KT*AST + QT*AST + KT) * 4)

__global__ __launch_bounds__(128, 1) void attn_tc(
    const float* __restrict__ qkv, const int* __restrict__ kpm,
    float* __restrict__ out)
{
    extern __shared__ float sm[];
    float* Qs   = sm;
    float* Kt   = Qs + QT * AST;
    float* Vs   = Kt + KT * AST;
    float* Ps   = Vs + KT * AST;
    float* padv = Ps + QT * AST;

    int qb = blockIdx.x, h = blockIdx.y, b = blockIdx.z;
    int tid = threadIdx.x, lane = tid & 31, warp = tid >> 5;
    int g = lane >> 2, t = lane & 3;
    const int lds = 3 * DIM_;
    const float scale = 0.125f;

    size_t qbase = ((size_t)(b * T_ + qb * QT)) * lds + h * HD_;
    for (int idx = tid; idx < QT * 16; idx += 128) {
        int r = idx >> 4, c4 = (idx & 15) * 4;
        float4 v = *(const float4*)(qkv + qbase + (size_t)r * lds + c4);
        Qs[r * AST + c4 + 0] = rtf32(v.x * scale);
        Qs[r * AST + c4 + 1] = rtf32(v.y * scale);
        Qs[r * AST + c4 + 2] = rtf32(v.z * scale);
        Qs[r * AST + c4 + 3] = rtf32(v.w * scale);
    }

    float m[2][2], l[2][2], o[2][8][4];
#pragma unroll
    for (int mt = 0; mt < 2; mt++)
#pragma unroll
        for (int hf = 0; hf < 2; hf++) { m[mt][hf] = -1e30f; l[mt][hf] = 0.f; }
#pragma unroll
    for (int mt = 0; mt < 2; mt++)
#pragma unroll
        for (int nt = 0; nt < 8; nt++)
#pragma unroll
            for (int i = 0; i < 4; i++) o[mt][nt][i] = 0.f;

    int ktiles = 2 * qb + 2;
    for (int kt = 0; kt < ktiles; kt++) {
        __syncthreads();
        size_t kbase = ((size_t)(b * T_ + kt * KT)) * lds + DIM_ + h * HD_;
        size_t vbase = kbase + DIM_;
        for (int idx = tid; idx < KT * 16; idx += 128) {
            int tok = idx & 63, d4 = (idx >> 6) * 4;
            float4 v = *(const float4*)(qkv + kbase + (size_t)tok * lds + d4);
            Kt[(d4 + 0) * AST + tok] = rtf32(v.x);
            Kt[(d4 + 1) * AST + tok] = rtf32(v.y);
            Kt[(d4 + 2) * AST + tok] = rtf32(v.z);
            Kt[(d4 + 3) * AST + tok] = rtf32(v.w);
        }
        for (int idx = tid; idx < KT * 16; idx += 128) {
            int tok = idx >> 4, d4 = (idx & 15) * 4;
            float4 v = *(const float4*)(qkv + vbase + (size_t)tok * lds + d4);
            v.x = rtf32(v.x); v.y = rtf32(v.y);
            v.z = rtf32(v.z); v.w = rtf32(v.w);
            *(float4*)&Vs[tok * AST + d4] = v;
        }
        if (tid < KT)
            padv[tid] = kpm[b * T_ + kt * KT + tid] ? -1e9f : 0.f;
        __syncthreads();

        float s[2][8][4];
#pragma unroll
        for (int mt = 0; mt < 2; mt++)
#pragma unroll
            for (int nt = 0; nt < 8; nt++)
#pragma unroll
                for (int i = 0; i < 4; i++) s[mt][nt][i] = 0.f;

#pragma unroll
        for (int k0 = 0; k0 < 64; k0 += 8) {
            unsigned af[2][4], bf[8][2];
#pragma unroll
            for (int mt = 0; mt < 2; mt++) {
                int r = warp * 32 + mt * 16 + g;
                af[mt][0] = __float_as_uint(Qs[r * AST + k0 + t]);
                af[mt][1] = __float_as_uint(Qs[(r + 8) * AST + k0 + t]);
                af[mt][2] = __float_as_uint(Qs[r * AST + k0 + t + 4]);
                af[mt][3] = __float_as_uint(Qs[(r + 8) * AST + k0 + t + 4]);
            }
#pragma unroll
            for (int nt = 0; nt < 8; nt++) {
                int n = nt * 8 + g;
                bf[nt][0] = __float_as_uint(Kt[(k0 + t) * AST + n]);
                bf[nt][1] = __float_as_uint(Kt[(k0 + t + 4) * AST + n]);
            }
#pragma unroll
            for (int mt = 0; mt < 2; mt++)
#pragma unroll
                for (int nt = 0; nt < 8; nt++)
                    mma_tf32(s[mt][nt], af[mt], bf[nt]);
        }

        float pv0[8], pv1[8];
#pragma unroll
        for (int nt = 0; nt < 8; nt++) {
            pv0[nt] = padv[nt * 8 + t * 2];
            pv1[nt] = padv[nt * 8 + t * 2 + 1];
        }
        bool dodiag = (kt >= 2 * qb);
#pragma unroll
        for (int mt = 0; mt < 2; mt++) {
#pragma unroll
            for (int hf = 0; hf < 2; hf++) {
                int rloc = warp * 32 + mt * 16 + g + hf * 8;
                int rglob = qb * QT + rloc;
                float tmax = -1e30f;
#pragma unroll
                for (int nt = 0; nt < 8; nt++) {
                    float v0 = s[mt][nt][hf * 2]     + pv0[nt];
                    float v1 = s[mt][nt][hf * 2 + 1] + pv1[nt];
                    if (dodiag) {
                        int c0 = kt * KT + nt * 8 + t * 2;
                        if (c0     > rglob) v0 = -1e30f;
                        if (c0 + 1 > rglob) v1 = -1e30f;
                    }
                    s[mt][nt][hf * 2]     = v0;
                    s[mt][nt][hf * 2 + 1] = v1;
                    tmax = fmaxf(tmax, fmaxf(v0, v1));
                }
                tmax = fmaxf(tmax, __shfl_xor_sync(0xffffffffu, tmax, 1));
                tmax = fmaxf(tmax, __shfl_xor_sync(0xffffffffu, tmax, 2));
                float mold = m[mt][hf];
                float mnew = fmaxf(mold, tmax);
                float al = __expf(mold - mnew);
                float rsum = 0.f;
#pragma unroll
                for (int nt = 0; nt < 8; nt++) {
                    float p0 = __expf(s[mt][nt][hf * 2]     - mnew);
                    float p1 = __expf(s[mt][nt][hf * 2 + 1] - mnew);
                    rsum += p0 + p1;
                    int c = nt * 8 + t * 2;
                    Ps[rloc * AST + c]     = rtf32(p0);
                    Ps[rloc * AST + c + 1] = rtf32(p1);
                }
                rsum += __shfl_xor_sync(0xffffffffu, rsum, 1);
                rsum += __shfl_xor_sync(0xffffffffu, rsum, 2);
                m[mt][hf] = mnew;
                l[mt][hf] = l[mt][hf] * al + rsum;
#pragma unroll
                for (int nt = 0; nt < 8; nt++) {
                    o[mt][nt][hf * 2]     *= al;
                    o[mt][nt][hf * 2 + 1] *= al;
                }
            }
        }
        __syncwarp();

#pragma unroll
        for (int k0 = 0; k0 < 64; k0 += 8) {
            unsigned af[2][4], bf[8][2];
#pragma unroll
            for (int mt = 0; mt < 2; mt++) {
                int r = warp * 32 + mt * 16 + g;
                af[mt][0] = __float_as_uint(Ps[r * AST + k0 + t]);
                af[mt][1] = __float_as_uint(Ps[(r + 8) * AST + k0 + t]);
                af[mt][2] = __float_as_uint(Ps[r * AST + k0 + t + 4]);
                af[mt][3] = __float_as_uint(Ps[(r + 8) * AST + k0 + t + 4]);
            }
#pragma unroll
            for (int nt = 0; nt < 8; nt++) {
                int d = nt * 8 + g;
                bf[nt][0] = __float_as_uint(Vs[(k0 + t) * AST + d]);
                bf[nt][1] = __float_as_uint(Vs[(k0 + t + 4) * AST + d]);
            }
#pragma unroll
            for (int mt = 0; mt < 2; mt++)
#pragma unroll
                for (int nt = 0; nt < 8; nt++)
                    mma_tf32(o[mt][nt], af[mt], bf[nt]);
        }
    }

#pragma unroll
    for (int mt = 0; mt < 2; mt++) {
#pragma unroll
        for (int hf = 0; hf < 2; hf++) {
            int rloc = warp * 32 + mt * 16 + g + hf * 8;
            float invl = 1.f / l[mt][hf];
            size_t ob = ((size_t)(b * T_ + qb * QT + rloc)) * DIM_ + h * HD_;
#pragma unroll
            for (int nt = 0; nt < 8; nt++) {
                int c = nt * 8 + t * 2;
                float2 v;
                v.x = rtf32(o[mt][nt][hf * 2]     * invl);
                v.y = rtf32(o[mt][nt][hf * 2 + 1] * invl);
                *(float2*)(out + ob + c) = v;
            }
        }
    }
}

// ---------------------------------------------------------------------------
extern "C" void kernel_launch(void* const* d_in, const int* in_sizes, int n_in,
                              void* d_out, int out_size)
{
    const float* x     = (const float*)d_in[0];
    const int*   kpm   = (const int*)  d_in[1];
    const float* ln1w  = (const float*)d_in[2];
    const float* ln1b  = (const float*)d_in[3];
    const float* qkvw  = (const float*)d_in[4];
    const float* projw = (const float*)d_in[5];
    const float* projb = (const float*)d_in[6];
    const float* ln2w  = (const float*)d_in[7];
    const float* ln2b  = (const float*)d_in[8];
    const float* fc1w  = (const float*)d_in[9];
    const float* fc1b  = (const float*)d_in[10];
    const float* fc2w  = (const float*)d_in[11];
    const float* fc2b  = (const float*)d_in[12];
    float* out = (float*)d_out;

    float *h1, *qkv, *att, *x2, *h2, *f1, *wq, *wp, *w1, *w2;
    cudaGetSymbolAddress((void**)&h1,  g_h1);
    cudaGetSymbolAddress((void**)&qkv, g_qkv);
    cudaGetSymbolAddress((void**)&att, g_att);
    cudaGetSymbolAddress((void**)&x2,  g_x2);
    cudaGetSymbolAddress((void**)&h2,  g_h2);
    cudaGetSymbolAddress((void**)&f1,  g_f1);
    cudaGetSymbolAddress((void**)&wq,  g_wq);
    cudaGetSymbolAddress((void**)&wp,  g_wp);
    cudaGetSymbolAddress((void**)&w1,  g_w1);
    cudaGetSymbolAddress((void**)&w2,  g_w2);

    cudaFuncSetAttribute(attn_tc,
        cudaFuncAttributeMaxDynamicSharedMemorySize, ATTN_SMEM);
    cudaFuncSetAttribute(gemm_tc<0>,
        cudaFuncAttributeMaxDynamicSharedMemorySize, GEMM_SMEM);
    cudaFuncSetAttribute(gemm_tc<1>,
        cudaFuncAttributeMaxDynamicSharedMemorySize, GEMM_SMEM);
    cudaFuncSetAttribute(gemm_tc<2>,
        cudaFuncAttributeMaxDynamicSharedMemorySize, GEMM_SMEM);

    // 0) transpose + tf32-round weights -> [N,K]
    transpose_tf32<<<dim3(DIM_/32, 3*DIM_/32), 256>>>(qkvw, wq, DIM_, 3*DIM_);
    transpose_tf32<<<dim3(DIM_/32, DIM_/32),   256>>>(projw, wp, DIM_, DIM_);
    transpose_tf32<<<dim3(DIM_/32, HID_/32),   256>>>(fc1w,  w1, DIM_, HID_);
    transpose_tf32<<<dim3(HID_/32, DIM_/32),   256>>>(fc2w,  w2, HID_, DIM_);

    // 1) LN1 (tf32-rounded)
    ln_kernel<<<NTOK, 256>>>(x, ln1w, ln1b, h1);
    // 2) QKV GEMM: [4096,1024] x Wt[3072,1024] -> [4096,3072]
    gemm_tc<0><<<dim3(3*DIM_/BN, NTOK/BM), 256, GEMM_SMEM>>>(
        h1, wq, nullptr, nullptr, qkv, NTOK, 3*DIM_, DIM_);
    // 3) Attention (tf32-rounded out)
    attn_tc<<<dim3(T_/QT, NH_, B_), 128, ATTN_SMEM>>>(qkv, kpm, att);
    // 4) proj GEMM + bias + residual(x)
    gemm_tc<1><<<dim3(DIM_/BN, NTOK/BM), 256, GEMM_SMEM>>>(
        att, wp, projb, x, x2, NTOK, DIM_, DIM_);
    // 5) LN2 (tf32-rounded)
    ln_kernel<<<NTOK, 256>>>(x2, ln2w, ln2b, h2);
    // 6) fc1 GEMM + bias + GELU (tf32-rounded)
    gemm_tc<2><<<dim3(HID_/BN, NTOK/BM), 256, GEMM_SMEM>>>(
        h2, w1, fc1b, nullptr, f1, NTOK, HID_, DIM_);
    // 7) fc2 GEMM + bias + residual(x2) -> out
    gemm_tc<1><<<dim3(DIM_/BN, NTOK/BM), 256, GEMM_SMEM>>>(
        f1, w2, fc2b, x2, out, NTOK, DIM_, HID_);
}

// round 8
// speedup vs baseline: 1.0704x; 1.0704x over previous
#include <cuda_runtime.h>
#include <math.h>
#include <cstdint>

#define B_    2
#define T_    2048
#define NTOK  4096
#define DIM_  1024
#define HID_  4096
#define NH_   16
#define HD_   64

// Scratch (allocation-free rule: __device__ globals)
__device__ float g_h1 [NTOK * DIM_];
__device__ float g_qkv[NTOK * 3 * DIM_];
__device__ float g_att[NTOK * DIM_];
__device__ float g_x2 [NTOK * DIM_];
__device__ float g_h2 [NTOK * DIM_];
__device__ float g_f1 [NTOK * HID_];
// tf32-rounded weights [K,N]
__device__ float g_wq [DIM_ * 3 * DIM_];
__device__ float g_wp [DIM_ * DIM_];
__device__ float g_w1 [DIM_ * HID_];
__device__ float g_w2 [HID_ * DIM_];

__device__ __forceinline__ unsigned f2tf32(float f) {
    unsigned u;
    asm("cvt.rna.tf32.f32 %0, %1;" : "=r"(u) : "f"(f));
    return u;
}
__device__ __forceinline__ float rtf32(float f) {
    return __uint_as_float(f2tf32(f));
}

// ---------------------------------------------------------------------------
// Elementwise tf32 rounding (weights), float4 vectorized
// ---------------------------------------------------------------------------
__global__ __launch_bounds__(256) void round4_kernel(
    const float* __restrict__ in, float* __restrict__ out, int n4)
{
    int i = blockIdx.x * 256 + threadIdx.x;
    if (i < n4) {
        float4 v = ((const float4*)in)[i];
        v.x = rtf32(v.x); v.y = rtf32(v.y);
        v.z = rtf32(v.z); v.w = rtf32(v.w);
        ((float4*)out)[i] = v;
    }
}

// ---------------------------------------------------------------------------
// LayerNorm: one block per row, 256 threads. Output rounded to tf32.
// ---------------------------------------------------------------------------
__global__ __launch_bounds__(256) void ln_kernel(
    const float* __restrict__ x, const float* __restrict__ w,
    const float* __restrict__ b, float* __restrict__ y)
{
    int row = blockIdx.x;
    const float* xr = x + (size_t)row * DIM_;
    float s = 0.f, s2 = 0.f;
    for (int i = threadIdx.x; i < DIM_; i += 256) {
        float v = xr[i]; s += v; s2 += v * v;
    }
    __shared__ float rs[8], rs2[8];
    for (int o = 16; o; o >>= 1) {
        s  += __shfl_down_sync(0xffffffffu, s,  o);
        s2 += __shfl_down_sync(0xffffffffu, s2, o);
    }
    int wid = threadIdx.x >> 5, lane = threadIdx.x & 31;
    if (!lane) { rs[wid] = s; rs2[wid] = s2; }
    __syncthreads();
    __shared__ float mu_s, inv_s;
    if (threadIdx.x == 0) {
        float t = 0.f, t2 = 0.f;
        for (int i = 0; i < 8; i++) { t += rs[i]; t2 += rs2[i]; }
        float mu = t / (float)DIM_;
        float var = t2 / (float)DIM_ - mu * mu;
        mu_s = mu;
        inv_s = rsqrtf(var + 1e-5f);
    }
    __syncthreads();
    float mu = mu_s, inv = inv_s;
    float* yr = y + (size_t)row * DIM_;
    for (int i = threadIdx.x; i < DIM_; i += 256)
        yr[i] = rtf32((xr[i] - mu) * inv * w[i] + b[i]);
}

// ---------------------------------------------------------------------------
// TF32 HMMA GEMM, cp.async 2-stage, 2 CTAs/SM.
// C[M,N] = A[M,K] * B[K,N] (row-major, pre-rounded to tf32).
// CTA tile 128x128, BK=16, 8 warps (2x4), warp tile 64x32.
// EPI: 0 none | 1 +bias+residual | 2 +bias+GELU(+tf32 round)
// ---------------------------------------------------------------------------
__device__ __forceinline__ void mma_tf32(float* c, const unsigned* a,
                                         const unsigned* b) {
    asm volatile(
        "mma.sync.aligned.m16n8k8.row.col.f32.tf32.tf32.f32 "
        "{%0,%1,%2,%3}, {%4,%5,%6,%7}, {%8,%9}, {%0,%1,%2,%3};"
        : "+f"(c[0]), "+f"(c[1]), "+f"(c[2]), "+f"(c[3])
        : "r"(a[0]), "r"(a[1]), "r"(a[2]), "r"(a[3]),
          "r"(b[0]), "r"(b[1]));
}

#define BM 128
#define BN 128
#define BKk 16
#define ASTR 20
#define BSTR 136
#define SA  (BM * ASTR)          // 2560 words
#define SBW (BKk * BSTR)         // 2176 words
#define SW  (SA + SBW)           // 4736 words
#define GEMM_SMEM (2 * SW * 4)   // 37888 B -> 2 CTAs/SM

#define CPASYNC16(dst, src) \
    asm volatile("cp.async.cg.shared.global [%0], [%1], 16;" \
                 :: "r"(dst), "l"(src))

template <int EPI>
__global__ __launch_bounds__(256, 2) void gemm_tc(
    const float* __restrict__ A, const float* __restrict__ Bm,
    const float* __restrict__ bias, const float* __restrict__ res,
    float* __restrict__ C, int M, int N, int K)
{
    extern __shared__ float smf[];
    unsigned sbase = (unsigned)__cvta_generic_to_shared(smf);

    int tid = threadIdx.x, lane = tid & 31, warp = tid >> 5;
    int wr = warp >> 2, wc = warp & 3;           // 2x4 warp grid, 64x32
    int row0 = blockIdx.y * BM, col0 = blockIdx.x * BN;
    int g = lane >> 2, t = lane & 3;

    const float* Ab = A  + (size_t)row0 * K;
    const float* Bb = Bm + col0;

    // producer mapping: A 512 chunks (2/thr), B 512 chunks (2/thr)
    int a_r = tid >> 2, a_c = (tid & 3) * 4;       // rows 0..63 (+64)
    int b_r = tid >> 5, b_c = (tid & 31) * 4;      // rows 0..7  (+8)

    float acc[4][4][4] = {};
    int iters = K / BKk;

#define LOAD_STAGE(st, kt) do {                                            \
        unsigned sa_ = sbase + (unsigned)((st) * SW) * 4u;                 \
        unsigned sb_ = sa_ + SA * 4u;                                      \
        int kof = (kt) * BKk;                                              \
        CPASYNC16(sa_ + (unsigned)(a_r * ASTR + a_c) * 4u,                 \
                  Ab + (size_t)a_r * K + kof + a_c);                       \
        CPASYNC16(sa_ + (unsigned)((a_r + 64) * ASTR + a_c) * 4u,          \
                  Ab + (size_t)(a_r + 64) * K + kof + a_c);                \
        CPASYNC16(sb_ + (unsigned)(b_r * BSTR + b_c) * 4u,                 \
                  Bb + (size_t)(kof + b_r) * N + b_c);                     \
        CPASYNC16(sb_ + (unsigned)((b_r + 8) * BSTR + b_c) * 4u,           \
                  Bb + (size_t)(kof + b_r + 8) * N + b_c);                 \
    } while (0)

    LOAD_STAGE(0, 0);
    asm volatile("cp.async.commit_group;");

    for (int it = 0; it < iters; it++) {
        int s = it & 1;
        if (it + 1 < iters) {
            LOAD_STAGE(s ^ 1, it + 1);      // other stage: safe (synced)
            asm volatile("cp.async.commit_group;");
            asm volatile("cp.async.wait_group 1;");
        } else {
            asm volatile("cp.async.wait_group 0;");
        }
        __syncthreads();

        const unsigned* As = (const unsigned*)(smf + s * SW);
        const unsigned* Bs = As + SA;
#pragma unroll
        for (int ks = 0; ks < 2; ks++) {
            int k0 = ks * 8;
            unsigned af[4][4], bf[4][2];
#pragma unroll
            for (int mt = 0; mt < 4; mt++) {
                int r = wr * 64 + mt * 16 + g;
                af[mt][0] = As[r * ASTR       + k0 + t];
                af[mt][1] = As[(r + 8) * ASTR + k0 + t];
                af[mt][2] = As[r * ASTR       + k0 + t + 4];
                af[mt][3] = As[(r + 8) * ASTR + k0 + t + 4];
            }
#pragma unroll
            for (int nt = 0; nt < 4; nt++) {
                int n = wc * 32 + nt * 8 + g;
                bf[nt][0] = Bs[(k0 + t) * BSTR     + n];
                bf[nt][1] = Bs[(k0 + t + 4) * BSTR + n];
            }
#pragma unroll
            for (int mt = 0; mt < 4; mt++)
#pragma unroll
                for (int nt = 0; nt < 4; nt++)
                    mma_tf32(acc[mt][nt], af[mt], bf[nt]);
        }
        __syncthreads();   // stage s may be overwritten next iteration
    }
#undef LOAD_STAGE

    // ---- epilogue ----
#pragma unroll
    for (int mt = 0; mt < 4; mt++) {
#pragma unroll
        for (int nt = 0; nt < 4; nt++) {
            int r = row0 + wr * 64 + mt * 16 + g;
            int c = col0 + wc * 32 + nt * 8 + t * 2;
#pragma unroll
            for (int half = 0; half < 2; half++) {
                int rr = r + half * 8;
                float v0 = acc[mt][nt][half * 2 + 0];
                float v1 = acc[mt][nt][half * 2 + 1];
                if (EPI == 1) {
                    const float* rp = res + (size_t)rr * N + c;
                    v0 += bias[c]     + rp[0];
                    v1 += bias[c + 1] + rp[1];
                } else if (EPI == 2) {
                    v0 += bias[c];
                    v1 += bias[c + 1];
                    v0 = 0.5f * v0 * (1.f + erff(v0 * 0.70710678118654752f));
                    v1 = 0.5f * v1 * (1.f + erff(v1 * 0.70710678118654752f));
                    v0 = rtf32(v0);
                    v1 = rtf32(v1);
                }
                *(float2*)(C + (size_t)rr * N + c) = make_float2(v0, v1);
            }
        }
    }
}

// ---------------------------------------------------------------------------
// Tensor-core flash attention (tf32 HMMA), causal + key-padding (R5).
// ---------------------------------------------------------------------------
#define QT 128
#define KT 64
#define AST 72
#define ATTN_SMEM ((QT*AST + KT*AST + KT*AST + QT*AST + KT) * 4)

__global__ __launch_bounds__(128, 1) void attn_tc(
    const float* __restrict__ qkv, const int* __restrict__ kpm,
    float* __restrict__ out)
{
    extern __shared__ float sm[];
    float* Qs   = sm;
    float* Kt   = Qs + QT * AST;
    float* Vs   = Kt + KT * AST;
    float* Ps   = Vs + KT * AST;
    float* padv = Ps + QT * AST;

    int qb = blockIdx.x, h = blockIdx.y, b = blockIdx.z;
    int tid = threadIdx.x, lane = tid & 31, warp = tid >> 5;
    int g = lane >> 2, t = lane & 3;
    const int lds = 3 * DIM_;
    const float scale = 0.125f;

    size_t qbase = ((size_t)(b * T_ + qb * QT)) * lds + h * HD_;
    for (int idx = tid; idx < QT * 16; idx += 128) {
        int r = idx >> 4, c4 = (idx & 15) * 4;
        float4 v = *(const float4*)(qkv + qbase + (size_t)r * lds + c4);
        Qs[r * AST + c4 + 0] = rtf32(v.x * scale);
        Qs[r * AST + c4 + 1] = rtf32(v.y * scale);
        Qs[r * AST + c4 + 2] = rtf32(v.z * scale);
        Qs[r * AST + c4 + 3] = rtf32(v.w * scale);
    }

    float m[2][2], l[2][2], o[2][8][4];
#pragma unroll
    for (int mt = 0; mt < 2; mt++)
#pragma unroll
        for (int hf = 0; hf < 2; hf++) { m[mt][hf] = -1e30f; l[mt][hf] = 0.f; }
#pragma unroll
    for (int mt = 0; mt < 2; mt++)
#pragma unroll
        for (int nt = 0; nt < 8; nt++)
#pragma unroll
            for (int i = 0; i < 4; i++) o[mt][nt][i] = 0.f;

    int ktiles = 2 * qb + 2;
    for (int kt = 0; kt < ktiles; kt++) {
        __syncthreads();
        size_t kbase = ((size_t)(b * T_ + kt * KT)) * lds + DIM_ + h * HD_;
        size_t vbase = kbase + DIM_;
        for (int idx = tid; idx < KT * 16; idx += 128) {
            int tok = idx & 63, d4 = (idx >> 6) * 4;
            float4 v = *(const float4*)(qkv + kbase + (size_t)tok * lds + d4);
            Kt[(d4 + 0) * AST + tok] = rtf32(v.x);
            Kt[(d4 + 1) * AST + tok] = rtf32(v.y);
            Kt[(d4 + 2) * AST + tok] = rtf32(v.z);
            Kt[(d4 + 3) * AST + tok] = rtf32(v.w);
        }
        for (int idx = tid; idx < KT * 16; idx += 128) {
            int tok = idx >> 4, d4 = (idx & 15) * 4;
            float4 v = *(const float4*)(qkv + vbase + (size_t)tok * lds + d4);
            v.x = rtf32(v.x); v.y = rtf32(v.y);
            v.z = rtf32(v.z); v.w = rtf32(v.w);
            *(float4*)&Vs[tok * AST + d4] = v;
        }
        if (tid < KT)
            padv[tid] = kpm[b * T_ + kt * KT + tid] ? -1e9f : 0.f;
        __syncthreads();

        float s[2][8][4];
#pragma unroll
        for (int mt = 0; mt < 2; mt++)
#pragma unroll
            for (int nt = 0; nt < 8; nt++)
#pragma unroll
                for (int i = 0; i < 4; i++) s[mt][nt][i] = 0.f;

#pragma unroll
        for (int k0 = 0; k0 < 64; k0 += 8) {
            unsigned af[2][4], bf[8][2];
#pragma unroll
            for (int mt = 0; mt < 2; mt++) {
                int r = warp * 32 + mt * 16 + g;
                af[mt][0] = __float_as_uint(Qs[r * AST + k0 + t]);
                af[mt][1] = __float_as_uint(Qs[(r + 8) * AST + k0 + t]);
                af[mt][2] = __float_as_uint(Qs[r * AST + k0 + t + 4]);
                af[mt][3] = __float_as_uint(Qs[(r + 8) * AST + k0 + t + 4]);
            }
#pragma unroll
            for (int nt = 0; nt < 8; nt++) {
                int n = nt * 8 + g;
                bf[nt][0] = __float_as_uint(Kt[(k0 + t) * AST + n]);
                bf[nt][1] = __float_as_uint(Kt[(k0 + t + 4) * AST + n]);
            }
#pragma unroll
            for (int mt = 0; mt < 2; mt++)
#pragma unroll
                for (int nt = 0; nt < 8; nt++)
                    mma_tf32(s[mt][nt], af[mt], bf[nt]);
        }

        float pv0[8], pv1[8];
#pragma unroll
        for (int nt = 0; nt < 8; nt++) {
            pv0[nt] = padv[nt * 8 + t * 2];
            pv1[nt] = padv[nt * 8 + t * 2 + 1];
        }
        bool dodiag = (kt >= 2 * qb);
#pragma unroll
        for (int mt = 0; mt < 2; mt++) {
#pragma unroll
            for (int hf = 0; hf < 2; hf++) {
                int rloc = warp * 32 + mt * 16 + g + hf * 8;
                int rglob = qb * QT + rloc;
                float tmax = -1e30f;
#pragma unroll
                for (int nt = 0; nt < 8; nt++) {
                    float v0 = s[mt][nt][hf * 2]     + pv0[nt];
                    float v1 = s[mt][nt][hf * 2 + 1] + pv1[nt];
                    if (dodiag) {
                        int c0 = kt * KT + nt * 8 + t * 2;
                        if (c0     > rglob) v0 = -1e30f;
                        if (c0 + 1 > rglob) v1 = -1e30f;
                    }
                    s[mt][nt][hf * 2]     = v0;
                    s[mt][nt][hf * 2 + 1] = v1;
                    tmax = fmaxf(tmax, fmaxf(v0, v1));
                }
                tmax = fmaxf(tmax, __shfl_xor_sync(0xffffffffu, tmax, 1));
                tmax = fmaxf(tmax, __shfl_xor_sync(0xffffffffu, tmax, 2));
                float mold = m[mt][hf];
                float mnew = fmaxf(mold, tmax);
                float al = __expf(mold - mnew);
                float rsum = 0.f;
#pragma unroll
                for (int nt = 0; nt < 8; nt++) {
                    float p0 = __expf(s[mt][nt][hf * 2]     - mnew);
                    float p1 = __expf(s[mt][nt][hf * 2 + 1] - mnew);
                    rsum += p0 + p1;
                    int c = nt * 8 + t * 2;
                    Ps[rloc * AST + c]     = rtf32(p0);
                    Ps[rloc * AST + c + 1] = rtf32(p1);
                }
                rsum += __shfl_xor_sync(0xffffffffu, rsum, 1);
                rsum += __shfl_xor_sync(0xffffffffu, rsum, 2);
                m[mt][hf] = mnew;
                l[mt][hf] = l[mt][hf] * al + rsum;
#pragma unroll
                for (int nt = 0; nt < 8; nt++) {
                    o[mt][nt][hf * 2]     *= al;
                    o[mt][nt][hf * 2 + 1] *= al;
                }
            }
        }
        __syncwarp();

#pragma unroll
        for (int k0 = 0; k0 < 64; k0 += 8) {
            unsigned af[2][4], bf[8][2];
#pragma unroll
            for (int mt = 0; mt < 2; mt++) {
                int r = warp * 32 + mt * 16 + g;
                af[mt][0] = __float_as_uint(Ps[r * AST + k0 + t]);
                af[mt][1] = __float_as_uint(Ps[(r + 8) * AST + k0 + t]);
                af[mt][2] = __float_as_uint(Ps[r * AST + k0 + t + 4]);
                af[mt][3] = __float_as_uint(Ps[(r + 8) * AST + k0 + t + 4]);
            }
#pragma unroll
            for (int nt = 0; nt < 8; nt++) {
                int d = nt * 8 + g;
                bf[nt][0] = __float_as_uint(Vs[(k0 + t) * AST + d]);
                bf[nt][1] = __float_as_uint(Vs[(k0 + t + 4) * AST + d]);
            }
#pragma unroll
            for (int mt = 0; mt < 2; mt++)
#pragma unroll
                for (int nt = 0; nt < 8; nt++)
                    mma_tf32(o[mt][nt], af[mt], bf[nt]);
        }
    }

#pragma unroll
    for (int mt = 0; mt < 2; mt++) {
#pragma unroll
        for (int hf = 0; hf < 2; hf++) {
            int rloc = warp * 32 + mt * 16 + g + hf * 8;
            float invl = 1.f / l[mt][hf];
            size_t ob = ((size_t)(b * T_ + qb * QT + rloc)) * DIM_ + h * HD_;
#pragma unroll
            for (int nt = 0; nt < 8; nt++) {
                int c = nt * 8 + t * 2;
                float2 v;
                v.x = rtf32(o[mt][nt][hf * 2]     * invl);
                v.y = rtf32(o[mt][nt][hf * 2 + 1] * invl);
                *(float2*)(out + ob + c) = v;
            }
        }
    }
}

// ---------------------------------------------------------------------------
extern "C" void kernel_launch(void* const* d_in, const int* in_sizes, int n_in,
                              void* d_out, int out_size)
{
    const float* x     = (const float*)d_in[0];
    const int*   kpm   = (const int*)  d_in[1];
    const float* ln1w  = (const float*)d_in[2];
    const float* ln1b  = (const float*)d_in[3];
    const float* qkvw  = (const float*)d_in[4];
    const float* projw = (const float*)d_in[5];
    const float* projb = (const float*)d_in[6];
    const float* ln2w  = (const float*)d_in[7];
    const float* ln2b  = (const float*)d_in[8];
    const float* fc1w  = (const float*)d_in[9];
    const float* fc1b  = (const float*)d_in[10];
    const float* fc2w  = (const float*)d_in[11];
    const float* fc2b  = (const float*)d_in[12];
    float* out = (float*)d_out;

    float *h1, *qkv, *att, *x2, *h2, *f1, *wq, *wp, *w1, *w2;
    cudaGetSymbolAddress((void**)&h1,  g_h1);
    cudaGetSymbolAddress((void**)&qkv, g_qkv);
    cudaGetSymbolAddress((void**)&att, g_att);
    cudaGetSymbolAddress((void**)&x2,  g_x2);
    cudaGetSymbolAddress((void**)&h2,  g_h2);
    cudaGetSymbolAddress((void**)&f1,  g_f1);
    cudaGetSymbolAddress((void**)&wq,  g_wq);
    cudaGetSymbolAddress((void**)&wp,  g_wp);
    cudaGetSymbolAddress((void**)&w1,  g_w1);
    cudaGetSymbolAddress((void**)&w2,  g_w2);

    cudaFuncSetAttribute(attn_tc,
        cudaFuncAttributeMaxDynamicSharedMemorySize, ATTN_SMEM);

    // 0) round weights to tf32
    round4_kernel<<<(DIM_*3*DIM_/4 + 255)/256, 256>>>(qkvw, wq, DIM_*3*DIM_/4);
    round4_kernel<<<(DIM_*DIM_/4   + 255)/256, 256>>>(projw, wp, DIM_*DIM_/4);
    round4_kernel<<<(DIM_*HID_/4   + 255)/256, 256>>>(fc1w,  w1, DIM_*HID_/4);
    round4_kernel<<<(HID_*DIM_/4   + 255)/256, 256>>>(fc2w,  w2, HID_*DIM_/4);

    // 1) LN1 (tf32-rounded)
    ln_kernel<<<NTOK, 256>>>(x, ln1w, ln1b, h1);
    // 2) QKV GEMM
    gemm_tc<0><<<dim3(3*DIM_/BN, NTOK/BM), 256, GEMM_SMEM>>>(
        h1, wq, nullptr, nullptr, qkv, NTOK, 3*DIM_, DIM_);
    // 3) Attention (tf32-rounded out)
    attn_tc<<<dim3(T_/QT, NH_, B_), 128, ATTN_SMEM>>>(qkv, kpm, att);
    // 4) proj GEMM + bias + residual(x)
    gemm_tc<1><<<dim3(DIM_/BN, NTOK/BM), 256, GEMM_SMEM>>>(
        att, wp, projb, x, x2, NTOK, DIM_, DIM_);
    // 5) LN2 (tf32-rounded)
    ln_kernel<<<NTOK, 256>>>(x2, ln2w, ln2b, h2);
    // 6) fc1 GEMM + bias + GELU (tf32-rounded)
    gemm_tc<2><<<dim3(HID_/BN, NTOK/BM), 256, GEMM_SMEM>>>(
        h2, w1, fc1b, nullptr, f1, NTOK, HID_, DIM_);
    // 7) fc2 GEMM + bias + residual(x2) -> out
    gemm_tc<1><<<dim3(DIM_/BN, NTOK/BM), 256, GEMM_SMEM>>>(
        f1, w2, fc2b, x2, out, NTOK, DIM_, HID_);
}

// round 9
// speedup vs baseline: 1.1245x; 1.0505x over previous
#include <cuda_runtime.h>
#include <math.h>
#include <cstdint>

#define B_    2
#define T_    2048
#define NTOK  4096
#define DIM_  1024
#define HID_  4096
#define NH_   16
#define HD_   64

// Scratch (allocation-free rule: __device__ globals)
__device__ float g_h1 [NTOK * DIM_];
__device__ float g_qkv[NTOK * 3 * DIM_];
__device__ float g_att[NTOK * DIM_];
__device__ float g_x2 [NTOK * DIM_];
__device__ float g_h2 [NTOK * DIM_];
__device__ float g_f1 [NTOK * HID_];
// tf32-rounded weights [K,N]
__device__ float g_wq [DIM_ * 3 * DIM_];
__device__ float g_wp [DIM_ * DIM_];
__device__ float g_w1 [DIM_ * HID_];
__device__ float g_w2 [HID_ * DIM_];

__device__ __forceinline__ unsigned f2tf32(float f) {
    unsigned u;
    asm("cvt.rna.tf32.f32 %0, %1;" : "=r"(u) : "f"(f));
    return u;
}
__device__ __forceinline__ float rtf32(float f) {
    return __uint_as_float(f2tf32(f));
}

// ---------------------------------------------------------------------------
// Elementwise tf32 rounding (weights), float4 vectorized
// ---------------------------------------------------------------------------
__global__ __launch_bounds__(256) void round4_kernel(
    const float* __restrict__ in, float* __restrict__ out, int n4)
{
    int i = blockIdx.x * 256 + threadIdx.x;
    if (i < n4) {
        float4 v = ((const float4*)in)[i];
        v.x = rtf32(v.x); v.y = rtf32(v.y);
        v.z = rtf32(v.z); v.w = rtf32(v.w);
        ((float4*)out)[i] = v;
    }
}

// ---------------------------------------------------------------------------
// LayerNorm: one block per row, 256 threads. Output rounded to tf32.
// ---------------------------------------------------------------------------
__global__ __launch_bounds__(256) void ln_kernel(
    const float* __restrict__ x, const float* __restrict__ w,
    const float* __restrict__ b, float* __restrict__ y)
{
    int row = blockIdx.x;
    const float* xr = x + (size_t)row * DIM_;
    float s = 0.f, s2 = 0.f;
    for (int i = threadIdx.x; i < DIM_; i += 256) {
        float v = xr[i]; s += v; s2 += v * v;
    }
    __shared__ float rs[8], rs2[8];
    for (int o = 16; o; o >>= 1) {
        s  += __shfl_down_sync(0xffffffffu, s,  o);
        s2 += __shfl_down_sync(0xffffffffu, s2, o);
    }
    int wid = threadIdx.x >> 5, lane = threadIdx.x & 31;
    if (!lane) { rs[wid] = s; rs2[wid] = s2; }
    __syncthreads();
    __shared__ float mu_s, inv_s;
    if (threadIdx.x == 0) {
        float t = 0.f, t2 = 0.f;
        for (int i = 0; i < 8; i++) { t += rs[i]; t2 += rs2[i]; }
        float mu = t / (float)DIM_;
        float var = t2 / (float)DIM_ - mu * mu;
        mu_s = mu;
        inv_s = rsqrtf(var + 1e-5f);
    }
    __syncthreads();
    float mu = mu_s, inv = inv_s;
    float* yr = y + (size_t)row * DIM_;
    for (int i = threadIdx.x; i < DIM_; i += 256)
        yr[i] = rtf32((xr[i] - mu) * inv * w[i] + b[i]);
}

// ---------------------------------------------------------------------------
// TF32 HMMA GEMM: CTA 128x128, 128 threads (4 warps 2x2, warp tile 64x64),
// BK=16, cp.async 3-stage ring, 2 CTAs/SM.
// C[M,N] = A[M,K] * B[K,N] (row-major, pre-rounded to tf32).
// EPI: 0 none | 1 +bias+residual | 2 +bias+GELU(+tf32 round)
// ---------------------------------------------------------------------------
__device__ __forceinline__ void mma_tf32(float* c, const unsigned* a,
                                         const unsigned* b) {
    asm volatile(
        "mma.sync.aligned.m16n8k8.row.col.f32.tf32.tf32.f32 "
        "{%0,%1,%2,%3}, {%4,%5,%6,%7}, {%8,%9}, {%0,%1,%2,%3};"
        : "+f"(c[0]), "+f"(c[1]), "+f"(c[2]), "+f"(c[3])
        : "r"(a[0]), "r"(a[1]), "r"(a[2]), "r"(a[3]),
          "r"(b[0]), "r"(b[1]));
}

#define BM 128
#define BN 128
#define BKk 16
#define ASTR 20
#define BSTR 136
#define SA  (BM * ASTR)          // 2560 words
#define SBW (BKk * BSTR)         // 2176 words
#define SW  (SA + SBW)           // 4736 words
#define NSTAGE 3
#define GEMM_SMEM (NSTAGE * SW * 4)   // 56832 B -> 2 CTAs/SM

#define CPASYNC16(dst, src) \
    asm volatile("cp.async.cg.shared.global [%0], [%1], 16;" \
                 :: "r"(dst), "l"(src))

template <int EPI>
__global__ __launch_bounds__(128, 2) void gemm_tc(
    const float* __restrict__ A, const float* __restrict__ Bm,
    const float* __restrict__ bias, const float* __restrict__ res,
    float* __restrict__ C, int M, int N, int K)
{
    extern __shared__ float smf[];
    unsigned sbase = (unsigned)__cvta_generic_to_shared(smf);

    int tid = threadIdx.x, lane = tid & 31, warp = tid >> 5;
    int wr = warp >> 1, wc = warp & 1;           // 2x2 warp grid, 64x64 each
    int row0 = blockIdx.y * BM, col0 = blockIdx.x * BN;
    int g = lane >> 2, t = lane & 3;

    const float* Ab = A  + (size_t)row0 * K;
    const float* Bb = Bm + col0;

    // producer mapping (128 threads): A 512 chunks (4/thr), B 512 (4/thr)
    int a_r = tid >> 2, a_c = (tid & 3) * 4;     // rows +32p
    int b_r = tid >> 5, b_c = (tid & 31) * 4;    // rows +4p

    float acc[4][8][4] = {};
    int iters = K / BKk;

#define LOAD_STAGE(st, kt) do {                                            \
        unsigned sa_ = sbase + (unsigned)((st) * SW) * 4u;                 \
        unsigned sb_ = sa_ + SA * 4u;                                      \
        int kof = (kt) * BKk;                                              \
        _Pragma("unroll")                                                  \
        for (int p = 0; p < 4; p++) {                                      \
            int r = a_r + 32 * p;                                          \
            CPASYNC16(sa_ + (unsigned)(r * ASTR + a_c) * 4u,               \
                      Ab + (size_t)r * K + kof + a_c);                     \
        }                                                                  \
        _Pragma("unroll")                                                  \
        for (int p = 0; p < 4; p++) {                                      \
            int r = b_r + 4 * p;                                           \
            CPASYNC16(sb_ + (unsigned)(r * BSTR + b_c) * 4u,               \
                      Bb + (size_t)(kof + r) * N + b_c);                   \
        }                                                                  \
    } while (0)

#pragma unroll
    for (int s = 0; s < NSTAGE - 1; s++) {
        LOAD_STAGE(s, s);
        asm volatile("cp.async.commit_group;");
    }

    for (int it = 0; it < iters; it++) {
        asm volatile("cp.async.wait_group 1;");
        __syncthreads();

        int nk = it + NSTAGE - 1;
        if (nk < iters) LOAD_STAGE(nk % NSTAGE, nk);
        asm volatile("cp.async.commit_group;");

        const unsigned* As = (const unsigned*)(smf + (it % NSTAGE) * SW);
        const unsigned* Bs = As + SA;
#pragma unroll
        for (int ks = 0; ks < 2; ks++) {
            int k0 = ks * 8;
            unsigned af[4][4], bf[8][2];
#pragma unroll
            for (int mt = 0; mt < 4; mt++) {
                int r = wr * 64 + mt * 16 + g;
                af[mt][0] = As[r * ASTR       + k0 + t];
                af[mt][1] = As[(r + 8) * ASTR + k0 + t];
                af[mt][2] = As[r * ASTR       + k0 + t + 4];
                af[mt][3] = As[(r + 8) * ASTR + k0 + t + 4];
            }
#pragma unroll
            for (int nt = 0; nt < 8; nt++) {
                int n = wc * 64 + nt * 8 + g;
                bf[nt][0] = Bs[(k0 + t) * BSTR     + n];
                bf[nt][1] = Bs[(k0 + t + 4) * BSTR + n];
            }
#pragma unroll
            for (int mt = 0; mt < 4; mt++)
#pragma unroll
                for (int nt = 0; nt < 8; nt++)
                    mma_tf32(acc[mt][nt], af[mt], bf[nt]);
        }
    }
#undef LOAD_STAGE

    // ---- epilogue ----
#pragma unroll
    for (int mt = 0; mt < 4; mt++) {
#pragma unroll
        for (int nt = 0; nt < 8; nt++) {
            int r = row0 + wr * 64 + mt * 16 + g;
            int c = col0 + wc * 64 + nt * 8 + t * 2;
#pragma unroll
            for (int half = 0; half < 2; half++) {
                int rr = r + half * 8;
                float v0 = acc[mt][nt][half * 2 + 0];
                float v1 = acc[mt][nt][half * 2 + 1];
                if (EPI == 1) {
                    const float* rp = res + (size_t)rr * N + c;
                    v0 += bias[c]     + rp[0];
                    v1 += bias[c + 1] + rp[1];
                } else if (EPI == 2) {
                    v0 += bias[c];
                    v1 += bias[c + 1];
                    v0 = 0.5f * v0 * (1.f + erff(v0 * 0.70710678118654752f));
                    v1 = 0.5f * v1 * (1.f + erff(v1 * 0.70710678118654752f));
                    v0 = rtf32(v0);
                    v1 = rtf32(v1);
                }
                *(float2*)(C + (size_t)rr * N + c) = make_float2(v0, v1);
            }
        }
    }
}

// ---------------------------------------------------------------------------
// Tensor-core flash attention (tf32 HMMA), causal + key-padding (R5).
// ---------------------------------------------------------------------------
#define QT 128
#define KT 64
#define AST 72
#define ATTN_SMEM ((QT*AST + KT*AST + KT*AST + QT*AST + KT) * 4)

__global__ __launch_bounds__(128, 1) void attn_tc(
    const float* __restrict__ qkv, const int* __restrict__ kpm,
    float* __restrict__ out)
{
    extern __shared__ float sm[];
    float* Qs   = sm;
    float* Kt   = Qs + QT * AST;
    float* Vs   = Kt + KT * AST;
    float* Ps   = Vs + KT * AST;
    float* padv = Ps + QT * AST;

    int qb = blockIdx.x, h = blockIdx.y, b = blockIdx.z;
    int tid = threadIdx.x, lane = tid & 31, warp = tid >> 5;
    int g = lane >> 2, t = lane & 3;
    const int lds = 3 * DIM_;
    const float scale = 0.125f;

    size_t qbase = ((size_t)(b * T_ + qb * QT)) * lds + h * HD_;
    for (int idx = tid; idx < QT * 16; idx += 128) {
        int r = idx >> 4, c4 = (idx & 15) * 4;
        float4 v = *(const float4*)(qkv + qbase + (size_t)r * lds + c4);
        Qs[r * AST + c4 + 0] = rtf32(v.x * scale);
        Qs[r * AST + c4 + 1] = rtf32(v.y * scale);
        Qs[r * AST + c4 + 2] = rtf32(v.z * scale);
        Qs[r * AST + c4 + 3] = rtf32(v.w * scale);
    }

    float m[2][2], l[2][2], o[2][8][4];
#pragma unroll
    for (int mt = 0; mt < 2; mt++)
#pragma unroll
        for (int hf = 0; hf < 2; hf++) { m[mt][hf] = -1e30f; l[mt][hf] = 0.f; }
#pragma unroll
    for (int mt = 0; mt < 2; mt++)
#pragma unroll
        for (int nt = 0; nt < 8; nt++)
#pragma unroll
            for (int i = 0; i < 4; i++) o[mt][nt][i] = 0.f;

    int ktiles = 2 * qb + 2;
    for (int kt = 0; kt < ktiles; kt++) {
        __syncthreads();
        size_t kbase = ((size_t)(b * T_ + kt * KT)) * lds + DIM_ + h * HD_;
        size_t vbase = kbase + DIM_;
        for (int idx = tid; idx < KT * 16; idx += 128) {
            int tok = idx & 63, d4 = (idx >> 6) * 4;
            float4 v = *(const float4*)(qkv + kbase + (size_t)tok * lds + d4);
            Kt[(d4 + 0) * AST + tok] = rtf32(v.x);
            Kt[(d4 + 1) * AST + tok] = rtf32(v.y);
            Kt[(d4 + 2) * AST + tok] = rtf32(v.z);
            Kt[(d4 + 3) * AST + tok] = rtf32(v.w);
        }
        for (int idx = tid; idx < KT * 16; idx += 128) {
            int tok = idx >> 4, d4 = (idx & 15) * 4;
            float4 v = *(const float4*)(qkv + vbase + (size_t)tok * lds + d4);
            v.x = rtf32(v.x); v.y = rtf32(v.y);
            v.z = rtf32(v.z); v.w = rtf32(v.w);
            *(float4*)&Vs[tok * AST + d4] = v;
        }
        if (tid < KT)
            padv[tid] = kpm[b * T_ + kt * KT + tid] ? -1e9f : 0.f;
        __syncthreads();

        float s[2][8][4];
#pragma unroll
        for (int mt = 0; mt < 2; mt++)
#pragma unroll
            for (int nt = 0; nt < 8; nt++)
#pragma unroll
                for (int i = 0; i < 4; i++) s[mt][nt][i] = 0.f;

#pragma unroll
        for (int k0 = 0; k0 < 64; k0 += 8) {
            unsigned af[2][4], bf[8][2];
#pragma unroll
            for (int mt = 0; mt < 2; mt++) {
                int r = warp * 32 + mt * 16 + g;
                af[mt][0] = __float_as_uint(Qs[r * AST + k0 + t]);
                af[mt][1] = __float_as_uint(Qs[(r + 8) * AST + k0 + t]);
                af[mt][2] = __float_as_uint(Qs[r * AST + k0 + t + 4]);
                af[mt][3] = __float_as_uint(Qs[(r + 8) * AST + k0 + t + 4]);
            }
#pragma unroll
            for (int nt = 0; nt < 8; nt++) {
                int n = nt * 8 + g;
                bf[nt][0] = __float_as_uint(Kt[(k0 + t) * AST + n]);
                bf[nt][1] = __float_as_uint(Kt[(k0 + t + 4) * AST + n]);
            }
#pragma unroll
            for (int mt = 0; mt < 2; mt++)
#pragma unroll
                for (int nt = 0; nt < 8; nt++)
                    mma_tf32(s[mt][nt], af[mt], bf[nt]);
        }

        float pv0[8], pv1[8];
#pragma unroll
        for (int nt = 0; nt < 8; nt++) {
            pv0[nt] = padv[nt * 8 + t * 2];
            pv1[nt] = padv[nt * 8 + t * 2 + 1];
        }
        bool dodiag = (kt >= 2 * qb);
#pragma unroll
        for (int mt = 0; mt < 2; mt++) {
#pragma unroll
            for (int hf = 0; hf < 2; hf++) {
                int rloc = warp * 32 + mt * 16 + g + hf * 8;
                int rglob = qb * QT + rloc;
                float tmax = -1e30f;
#pragma unroll
                for (int nt = 0; nt < 8; nt++) {
                    float v0 = s[mt][nt][hf * 2]     + pv0[nt];
                    float v1 = s[mt][nt][hf * 2 + 1] + pv1[nt];
                    if (dodiag) {
                        int c0 = kt * KT + nt * 8 + t * 2;
                        if (c0     > rglob) v0 = -1e30f;
                        if (c0 + 1 > rglob) v1 = -1e30f;
                    }
                    s[mt][nt][hf * 2]     = v0;
                    s[mt][nt][hf * 2 + 1] = v1;
                    tmax = fmaxf(tmax, fmaxf(v0, v1));
                }
                tmax = fmaxf(tmax, __shfl_xor_sync(0xffffffffu, tmax, 1));
                tmax = fmaxf(tmax, __shfl_xor_sync(0xffffffffu, tmax, 2));
                float mold = m[mt][hf];
                float mnew = fmaxf(mold, tmax);
                float al = __expf(mold - mnew);
                float rsum = 0.f;
#pragma unroll
                for (int nt = 0; nt < 8; nt++) {
                    float p0 = __expf(s[mt][nt][hf * 2]     - mnew);
                    float p1 = __expf(s[mt][nt][hf * 2 + 1] - mnew);
                    rsum += p0 + p1;
                    int c = nt * 8 + t * 2;
                    Ps[rloc * AST + c]     = rtf32(p0);
                    Ps[rloc * AST + c + 1] = rtf32(p1);
                }
                rsum += __shfl_xor_sync(0xffffffffu, rsum, 1);
                rsum += __shfl_xor_sync(0xffffffffu, rsum, 2);
                m[mt][hf] = mnew;
                l[mt][hf] = l[mt][hf] * al + rsum;
#pragma unroll
                for (int nt = 0; nt < 8; nt++) {
                    o[mt][nt][hf * 2]     *= al;
                    o[mt][nt][hf * 2 + 1] *= al;
                }
            }
        }
        __syncwarp();

#pragma unroll
        for (int k0 = 0; k0 < 64; k0 += 8) {
            unsigned af[2][4], bf[8][2];
#pragma unroll
            for (int mt = 0; mt < 2; mt++) {
                int r = warp * 32 + mt * 16 + g;
                af[mt][0] = __float_as_uint(Ps[r * AST + k0 + t]);
                af[mt][1] = __float_as_uint(Ps[(r + 8) * AST + k0 + t]);
                af[mt][2] = __float_as_uint(Ps[r * AST + k0 + t + 4]);
                af[mt][3] = __float_as_uint(Ps[(r + 8) * AST + k0 + t + 4]);
            }
#pragma unroll
            for (int nt = 0; nt < 8; nt++) {
                int d = nt * 8 + g;
                bf[nt][0] = __float_as_uint(Vs[(k0 + t) * AST + d]);
                bf[nt][1] = __float_as_uint(Vs[(k0 + t + 4) * AST + d]);
            }
#pragma unroll
            for (int mt = 0; mt < 2; mt++)
#pragma unroll
                for (int nt = 0; nt < 8; nt++)
                    mma_tf32(o[mt][nt], af[mt], bf[nt]);
        }
    }

#pragma unroll
    for (int mt = 0; mt < 2; mt++) {
#pragma unroll
        for (int hf = 0; hf < 2; hf++) {
            int rloc = warp * 32 + mt * 16 + g + hf * 8;
            float invl = 1.f / l[mt][hf];
            size_t ob = ((size_t)(b * T_ + qb * QT + rloc)) * DIM_ + h * HD_;
#pragma unroll
            for (int nt = 0; nt < 8; nt++) {
                int c = nt * 8 + t * 2;
                float2 v;
                v.x = rtf32(o[mt][nt][hf * 2]     * invl);
                v.y = rtf32(o[mt][nt][hf * 2 + 1] * invl);
                *(float2*)(out + ob + c) = v;
            }
        }
    }
}

// ---------------------------------------------------------------------------
extern "C" void kernel_launch(void* const* d_in, const int* in_sizes, int n_in,
                              void* d_out, int out_size)
{
    const float* x     = (const float*)d_in[0];
    const int*   kpm   = (const int*)  d_in[1];
    const float* ln1w  = (const float*)d_in[2];
    const float* ln1b  = (const float*)d_in[3];
    const float* qkvw  = (const float*)d_in[4];
    const float* projw = (const float*)d_in[5];
    const float* projb = (const float*)d_in[6];
    const float* ln2w  = (const float*)d_in[7];
    const float* ln2b  = (const float*)d_in[8];
    const float* fc1w  = (const float*)d_in[9];
    const float* fc1b  = (const float*)d_in[10];
    const float* fc2w  = (const float*)d_in[11];
    const float* fc2b  = (const float*)d_in[12];
    float* out = (float*)d_out;

    float *h1, *qkv, *att, *x2, *h2, *f1, *wq, *wp, *w1, *w2;
    cudaGetSymbolAddress((void**)&h1,  g_h1);
    cudaGetSymbolAddress((void**)&qkv, g_qkv);
    cudaGetSymbolAddress((void**)&att, g_att);
    cudaGetSymbolAddress((void**)&x2,  g_x2);
    cudaGetSymbolAddress((void**)&h2,  g_h2);
    cudaGetSymbolAddress((void**)&f1,  g_f1);
    cudaGetSymbolAddress((void**)&wq,  g_wq);
    cudaGetSymbolAddress((void**)&wp,  g_wp);
    cudaGetSymbolAddress((void**)&w1,  g_w1);
    cudaGetSymbolAddress((void**)&w2,  g_w2);

    cudaFuncSetAttribute(attn_tc,
        cudaFuncAttributeMaxDynamicSharedMemorySize, ATTN_SMEM);
    cudaFuncSetAttribute(gemm_tc<0>,
        cudaFuncAttributeMaxDynamicSharedMemorySize, GEMM_SMEM);
    cudaFuncSetAttribute(gemm_tc<1>,
        cudaFuncAttributeMaxDynamicSharedMemorySize, GEMM_SMEM);
    cudaFuncSetAttribute(gemm_tc<2>,
        cudaFuncAttributeMaxDynamicSharedMemorySize, GEMM_SMEM);

    // 0) round weights to tf32
    round4_kernel<<<(DIM_*3*DIM_/4 + 255)/256, 256>>>(qkvw, wq, DIM_*3*DIM_/4);
    round4_kernel<<<(DIM_*DIM_/4   + 255)/256, 256>>>(projw, wp, DIM_*DIM_/4);
    round4_kernel<<<(DIM_*HID_/4   + 255)/256, 256>>>(fc1w,  w1, DIM_*HID_/4);
    round4_kernel<<<(HID_*DIM_/4   + 255)/256, 256>>>(fc2w,  w2, HID_*DIM_/4);

    // 1) LN1 (tf32-rounded)
    ln_kernel<<<NTOK, 256>>>(x, ln1w, ln1b, h1);
    // 2) QKV GEMM
    gemm_tc<0><<<dim3(3*DIM_/BN, NTOK/BM), 128, GEMM_SMEM>>>(
        h1, wq, nullptr, nullptr, qkv, NTOK, 3*DIM_, DIM_);
    // 3) Attention (tf32-rounded out)
    attn_tc<<<dim3(T_/QT, NH_, B_), 128, ATTN_SMEM>>>(qkv, kpm, att);
    // 4) proj GEMM + bias + residual(x)
    gemm_tc<1><<<dim3(DIM_/BN, NTOK/BM), 128, GEMM_SMEM>>>(
        att, wp, projb, x, x2, NTOK, DIM_, DIM_);
    // 5) LN2 (tf32-rounded)
    ln_kernel<<<NTOK, 256>>>(x2, ln2w, ln2b, h2);
    // 6) fc1 GEMM + bias + GELU (tf32-rounded)
    gemm_tc<2><<<dim3(HID_/BN, NTOK/BM), 128, GEMM_SMEM>>>(
        h2, w1, fc1b, nullptr, f1, NTOK, HID_, DIM_);
    // 7) fc2 GEMM + bias + residual(x2) -> out
    gemm_tc<1><<<dim3(DIM_/BN, NTOK/BM), 128, GEMM_SMEM>>>(
        f1, w2, fc2b, x2, out, NTOK, DIM_, HID_);
}